// round 14
// baseline (speedup 1.0000x reference)
#include <cuda_runtime.h>
#include <cuda_fp16.h>
#include <string.h>

#define NM 128
#define NM3 (NM * NM * NM)
#define NC 16
#define NPTS 100000
#define INV_SPACING 10.0f

// Two half-channel scratch buffers, (x,y,z, ch-half) fp16 layout.
// One half-cell = 8 halfs = 16 bytes; stored as 32B pairs (z even/odd) so
// transpose stores can carry L2::evict_last (needs 256-bit access).
// 33.5 MB each -> ~27% of L2; consumed IMMEDIATELY after being produced.
__device__ ulonglong4 g_scrA[NM3 / 2];   // channels 0..7
__device__ ulonglong4 g_scrB[NM3 / 2];   // channels 8..15

static __device__ __forceinline__ unsigned h2u(__half2 h) {
    unsigned u; memcpy(&u, &h, 4); return u;
}
static __device__ __forceinline__ __half2 u2h(unsigned u) {
    __half2 h; memcpy(&h, &u, 4); return h;
}
static __device__ __forceinline__ unsigned long long pack64(unsigned lo, unsigned hi) {
    return (unsigned long long)lo | ((unsigned long long)hi << 32);
}
static __device__ __forceinline__ void st_pair_evict_last(ulonglong4* p, ulonglong4 v) {
    asm volatile("st.global.L2::evict_last.v4.b64 [%0], {%1,%2,%3,%4};"
                 :: "l"(p), "l"(v.x), "l"(v.y), "l"(v.z), "l"(v.w) : "memory");
}

// ---------------------------------------------------------------------------
// Transpose one channel-half: (c, cell)f32 -> (cell, c-half)f16.
// One thread per 8 consecutive z-cells: 16 LDG.128.cs reads (streaming,
// evict-first), 4 STG.256 evict_last writes (each covers 2 cells).
// ---------------------------------------------------------------------------
__global__ void transpose_half_kernel(const float* __restrict__ in, int cbase,
                                      ulonglong4* __restrict__ dst) {
    int t = blockIdx.x * blockDim.x + threadIdx.x;   // 0 .. NM3/8-1
    int cell0 = t * 8;

    float4 v[8][2];
#pragma unroll
    for (int c = 0; c < 8; c++) {
        const float4* p = (const float4*)(in + (size_t)(cbase + c) * NM3 + cell0);
        v[c][0] = __ldcs(p);
        v[c][1] = __ldcs(p + 1);
    }

#pragma unroll
    for (int k = 0; k < 4; k++) {        // z-pair (2k, 2k+1)
        int h = k >> 1;                  // which float4 half
        float f0[8], f1[8];
#pragma unroll
        for (int c = 0; c < 8; c++) {
            float4 q = v[c][h];
            if ((k & 1) == 0) { f0[c] = q.x; f1[c] = q.y; }
            else              { f0[c] = q.z; f1[c] = q.w; }
        }
        ulonglong4 o;
        o.x = pack64(h2u(__floats2half2_rn(f0[0], f0[1])),
                     h2u(__floats2half2_rn(f0[2], f0[3])));
        o.y = pack64(h2u(__floats2half2_rn(f0[4], f0[5])),
                     h2u(__floats2half2_rn(f0[6], f0[7])));
        o.z = pack64(h2u(__floats2half2_rn(f1[0], f1[1])),
                     h2u(__floats2half2_rn(f1[2], f1[3])));
        o.w = pack64(h2u(__floats2half2_rn(f1[4], f1[5])),
                     h2u(__floats2half2_rn(f1[6], f1[7])));
        st_pair_evict_last(&dst[t * 4 + k], o);
    }
}

// ---------------------------------------------------------------------------
// Interp one channel-half: 1 thread per point, 27 independent 16B taps
// (8 channels each), fp32 weights/accum, 32B output per point.
// Runs immediately after its producer transpose -> scratch should be L2-hot.
// ---------------------------------------------------------------------------
__global__ void interp_half_kernel(const float* __restrict__ points,
                                   const uint4* __restrict__ scr,
                                   float4* __restrict__ out, int ohalf) {
    int p = blockIdx.x * blockDim.x + threadIdx.x;
    if (p >= NPTS) return;

    float px = points[p * 3 + 0] * INV_SPACING;
    float py = points[p * 3 + 1] * INV_SPACING;
    float pz = points[p * 3 + 2] * INV_SPACING;

    float rx = rintf(px), ry = rintf(py), rz = rintf(pz);
    float dx = px - rx, dy = py - ry, dz = pz - rz;
    int ix = (int)rx, iy = (int)ry, iz = (int)rz;

    float wx[3], wy[3], wz[3];
    {
        float a;
        a = 2.0f * dx - 1.0f; wx[0] = a * a * 0.125f;
        wx[1] = 0.75f - dx * dx;
        a = 2.0f * dx + 1.0f; wx[2] = a * a * 0.125f;

        a = 2.0f * dy - 1.0f; wy[0] = a * a * 0.125f;
        wy[1] = 0.75f - dy * dy;
        a = 2.0f * dy + 1.0f; wy[2] = a * a * 0.125f;

        a = 2.0f * dz - 1.0f; wz[0] = a * a * 0.125f;
        wz[1] = 0.75f - dz * dz;
        a = 2.0f * dz + 1.0f; wz[2] = a * a * 0.125f;
    }

    int xs[3], ys[3], zs[3];
    xs[0] = (ix + 127) & (NM - 1); xs[1] = ix & (NM - 1); xs[2] = (ix + 129) & (NM - 1);
    ys[0] = (iy + 127) & (NM - 1); ys[1] = iy & (NM - 1); ys[2] = (iy + 129) & (NM - 1);
    zs[0] = (iz + 127) & (NM - 1); zs[1] = iz & (NM - 1); zs[2] = (iz + 129) & (NM - 1);

    float acc[8];
#pragma unroll
    for (int c = 0; c < 8; c++) acc[c] = 0.0f;

#pragma unroll
    for (int ox = 0; ox < 3; ox++) {
#pragma unroll
        for (int oy = 0; oy < 3; oy++) {
            float wxy = wx[ox] * wy[oy];
            int rowbase = (xs[ox] * NM + ys[oy]) * NM;
#pragma unroll
            for (int oz = 0; oz < 3; oz++) {
                float w = wxy * wz[oz];
                uint4 raw = __ldg(&scr[rowbase + zs[oz]]);
                float2 f0 = __half22float2(u2h(raw.x));
                float2 f1 = __half22float2(u2h(raw.y));
                float2 f2 = __half22float2(u2h(raw.z));
                float2 f3 = __half22float2(u2h(raw.w));
                acc[0] += w * f0.x; acc[1] += w * f0.y;
                acc[2] += w * f1.x; acc[3] += w * f1.y;
                acc[4] += w * f2.x; acc[5] += w * f2.y;
                acc[6] += w * f3.x; acc[7] += w * f3.y;
            }
        }
    }

    float4* o = out + (size_t)p * 4 + ohalf;
    __stcs(o + 0, make_float4(acc[0], acc[1], acc[2], acc[3]));
    __stcs(o + 1, make_float4(acc[4], acc[5], acc[6], acc[7]));
}

extern "C" void kernel_launch(void* const* d_in, const int* in_sizes, int n_in,
                              void* d_out, int out_size) {
    const float* mesh = (const float*)d_in[0];    // (16, 128, 128, 128) f32
    const float* points = (const float*)d_in[1];  // (100000, 3) f32
    float4* out = (float4*)d_out;                 // (100000, 16) f32

    ulonglong4* scrA; cudaGetSymbolAddress((void**)&scrA, g_scrA);
    ulonglong4* scrB; cudaGetSymbolAddress((void**)&scrB, g_scrB);

    const int tThreads = 256, tBlocks = (NM3 / 8) / tThreads;              // 1024
    const int iThreads = 256, iBlocks = (NPTS + iThreads - 1) / iThreads;  // 391

    // SINGLE stream, producer -> consumer adjacency:
    // interp A runs while scratch A is still L2-hot, before transpose B
    // streams anything new through L2. Same for half B.
    transpose_half_kernel<<<tBlocks, tThreads>>>(mesh, 0, scrA);
    interp_half_kernel<<<iBlocks, iThreads>>>(points, (const uint4*)scrA, out, 0);
    transpose_half_kernel<<<tBlocks, tThreads>>>(mesh, 8, scrB);
    interp_half_kernel<<<iBlocks, iThreads>>>(points, (const uint4*)scrB, out, 2);
}